// round 15
// baseline (speedup 1.0000x reference)
#include <cuda_runtime.h>
#include <cuda_fp16.h>
#include <math.h>
#include <stdint.h>

#define NN 20000
#define MM 32
#define INDIM 256
#define OUTDIM 256
#define NHEAD 4
#define HDIM 64
#define LN_EPS 1e-5f
#define NEG_INF -1.0e9f

// scratch buffers (fp16 pairs packed in uint32)
__device__ uint32_t g_hproj_h2[NN * OUTDIM / 2];  // fp16 h_proj (~10.2 MB)
__device__ float    g_el[NN * NHEAD];
__device__ float    g_er[NN * NHEAD];

// ----------------------------------------------------------------------------
// PTX helpers
// ----------------------------------------------------------------------------
__device__ __forceinline__ void ldsm_x4(uint32_t& r0, uint32_t& r1, uint32_t& r2,
                                        uint32_t& r3, uint32_t addr) {
    asm volatile("ldmatrix.sync.aligned.m8n8.x4.shared.b16 {%0,%1,%2,%3}, [%4];"
                 : "=r"(r0), "=r"(r1), "=r"(r2), "=r"(r3) : "r"(addr));
}
__device__ __forceinline__ void ldsm_x4_t(uint32_t& r0, uint32_t& r1, uint32_t& r2,
                                          uint32_t& r3, uint32_t addr) {
    asm volatile("ldmatrix.sync.aligned.m8n8.x4.trans.shared.b16 {%0,%1,%2,%3}, [%4];"
                 : "=r"(r0), "=r"(r1), "=r"(r2), "=r"(r3) : "r"(addr));
}
__device__ __forceinline__ void mma_f16(float* d, const uint32_t* a, const uint32_t* b) {
    asm volatile(
        "mma.sync.aligned.m16n8k16.row.col.f32.f16.f16.f32 "
        "{%0,%1,%2,%3}, {%4,%5,%6,%7}, {%8,%9}, {%0,%1,%2,%3};"
        : "+f"(d[0]), "+f"(d[1]), "+f"(d[2]), "+f"(d[3])
        : "r"(a[0]), "r"(a[1]), "r"(a[2]), "r"(a[3]), "r"(b[0]), "r"(b[1]));
}
__device__ __forceinline__ uint32_t packh2(float x, float y) {
    __half2 h = __float22half2_rn(make_float2(x, y));
    return *reinterpret_cast<uint32_t*>(&h);
}

// ----------------------------------------------------------------------------
// Kernel 1: h_proj = h @ W, fp16 mma.sync m16n8k16. BOTH operands staged from
// fp32 gmem with fused conversion (LDG.128 + cvt + STS); no convert kernels,
// no fp16 gmem copies of inputs, no cp.async.
// Block tile 128x64, BK=32, 256 threads (8 warps: 4M x 2N), warp tile 32x32.
// A: held-register prefetch one iteration ahead. B: adjacent load+store at
// loop bottom (W is L2-resident, ~234cyc, hidden by 16 warps/SM).
// One __syncthreads per iteration; 4 smem stages.
// Epilogue computes el/er for head blockIdx.y.
// ----------------------------------------------------------------------------
#define BKG 32
#define A_ST 40
#define B_ST 72
#define A_HALFS (128 * A_ST)
#define B_HALFS (BKG * B_ST)
#define STAGE_BYTES ((A_HALFS + B_HALFS) * 2)
#define NSTG 4
#define GEMM_SMEM_BYTES (NSTG * STAGE_BYTES)

__global__ __launch_bounds__(256, 2)
void gemm_f16_kernel(const float* __restrict__ h, const float* __restrict__ W,
                     const float* __restrict__ a_l, const float* __restrict__ a_r) {
    extern __shared__ uint8_t dynsm[];
    const uint32_t smem_base = (uint32_t)__cvta_generic_to_shared(dynsm);
    __shared__ float s_e2[2][128][2];   // [wn][row][el/er]

    const int tid = threadIdx.x;
    const int lane = tid & 31;
    const int w = tid >> 5;
    const int wm = w & 3;
    const int wn = w >> 2;
    const int m0w = wm * 32;
    const int n0w = wn * 32;

    const int rowBase = blockIdx.x * 128;
    const int nBase = blockIdx.y * 64;

    // A fp32 load mapping: rows af_row+32q, float cols af_col..af_col+3
    const int af_row = tid >> 3;          // 0..31
    const int af_col = (tid & 7) * 4;     // 0,4,...,28
    // B fp32 load mapping: row bf_row, float cols bf_col..bf_col+7
    const int bf_row = tid >> 3;          // 0..31
    const int bf_col = (tid & 7) * 8;     // 0,8,...,56

    auto loadA = [&](float4* areg, int kt) {
#pragma unroll
        for (int q = 0; q < 4; q++) {
            int gr = rowBase + af_row + 32 * q;
            areg[q] = (gr < NN)
                ? *reinterpret_cast<const float4*>(&h[gr * INDIM + kt + af_col])
                : make_float4(0.f, 0.f, 0.f, 0.f);
        }
    };
    auto stsA = [&](const float4* areg, int stage) {
        uint8_t* aB = dynsm + stage * STAGE_BYTES;
#pragma unroll
        for (int q = 0; q < 4; q++) {
            int r = af_row + 32 * q;
            uint2 p = make_uint2(packh2(areg[q].x, areg[q].y),
                                 packh2(areg[q].z, areg[q].w));
            *reinterpret_cast<uint2*>(aB + (r * A_ST + af_col) * 2) = p;
        }
    };
    auto fillB = [&](int stage, int kt) {
        const float4* src = reinterpret_cast<const float4*>(
            &W[(kt + bf_row) * OUTDIM + nBase + bf_col]);
        float4 v0 = src[0], v1 = src[1];
        uint4 p = make_uint4(packh2(v0.x, v0.y), packh2(v0.z, v0.w),
                             packh2(v1.x, v1.y), packh2(v1.z, v1.w));
        uint8_t* bB = dynsm + stage * STAGE_BYTES + A_HALFS * 2;
        *reinterpret_cast<uint4*>(bB + (bf_row * B_ST + bf_col) * 2) = p;
    };

    float acc[2][4][4];
#pragma unroll
    for (int i = 0; i < 2; i++)
#pragma unroll
        for (int j = 0; j < 4; j++)
#pragma unroll
            for (int k = 0; k < 4; k++) acc[i][j][k] = 0.0f;

    const int r8 = lane & 7;
    const int quad = lane >> 3;
    const int qRow = (quad & 1) << 3;
    const int qCol = (quad >> 1) << 3;

    // ---- prologue: fill stages 0,1; prefetch A regs for stage 2 ----
    float4 areg[4];
    loadA(areg, 0);        stsA(areg, 0);  fillB(0, 0);
    loadA(areg, BKG);      stsA(areg, 1);  fillB(1, BKG);
    loadA(areg, 2 * BKG);  // held for stage 2

    const int NITER = INDIM / BKG;   // 8
    for (int it = 0; it < NITER; it++) {
        __syncthreads();   // publish stage it; guard overwrite of stage it+2
        const uint32_t sA = smem_base + (it & (NSTG - 1)) * STAGE_BYTES;
        const uint32_t sB = sA + A_HALFS * 2;

#pragma unroll
        for (int g = 0; g < 2; g++) {
            const int k0 = g * 16;
            uint32_t a[2][4];
#pragma unroll
            for (int tm = 0; tm < 2; tm++) {
                uint32_t addr = sA + ((m0w + tm * 16 + qRow + r8) * A_ST + k0 + qCol) * 2;
                ldsm_x4(a[tm][0], a[tm][1], a[tm][2], a[tm][3], addr);
            }
            uint32_t b[2][4];
#pragma unroll
            for (int t2 = 0; t2 < 2; t2++) {
                uint32_t addr = sB + ((k0 + qRow + r8) * B_ST + n0w + t2 * 16 + qCol) * 2;
                ldsm_x4_t(b[t2][0], b[t2][1], b[t2][2], b[t2][3], addr);
            }
#pragma unroll
            for (int tm = 0; tm < 2; tm++)
#pragma unroll
                for (int tn = 0; tn < 4; tn++) {
                    uint32_t bb[2] = { b[tn >> 1][2 * (tn & 1)], b[tn >> 1][2 * (tn & 1) + 1] };
                    mma_f16(acc[tm][tn], a[tm], bb);
                }
        }

        // fill stage it+2: A from held regs, B adjacent; prefetch A for it+3
        if (it + 2 < NITER) {
            stsA(areg, (it + 2) & (NSTG - 1));
            fillB((it + 2) & (NSTG - 1), (it + 2) * BKG);
            if (it + 3 < NITER)
                loadA(areg, (it + 3) * BKG);
        }
    }

    const int lr = lane >> 2;
    const int lc = lane & 3;

    // ---- el/er partials for head blockIdx.y ----
    float alv[8], arv[8];
#pragma unroll
    for (int tn = 0; tn < 4; tn++)
#pragma unroll
        for (int kk = 0; kk < 2; kk++) {
            int c = nBase + n0w + tn * 8 + 2 * lc + kk;
            alv[tn * 2 + kk] = a_l[c];
            arv[tn * 2 + kk] = a_r[c];
        }
    float elp[4] = {0.f, 0.f, 0.f, 0.f};
    float erp[4] = {0.f, 0.f, 0.f, 0.f};
#pragma unroll
    for (int tm = 0; tm < 2; tm++)
#pragma unroll
        for (int tn = 0; tn < 4; tn++)
#pragma unroll
            for (int k = 0; k < 4; k++) {
                int ridx = tm * 2 + (k >> 1);
                float av = alv[tn * 2 + (k & 1)];
                float rv = arv[tn * 2 + (k & 1)];
                elp[ridx] = fmaf(acc[tm][tn][k], av, elp[ridx]);
                erp[ridx] = fmaf(acc[tm][tn][k], rv, erp[ridx]);
            }
#pragma unroll
    for (int off = 1; off <= 2; off <<= 1)
#pragma unroll
        for (int i = 0; i < 4; i++) {
            elp[i] += __shfl_xor_sync(0xffffffffu, elp[i], off);
            erp[i] += __shfl_xor_sync(0xffffffffu, erp[i], off);
        }
    if (lc == 0) {
#pragma unroll
        for (int tm = 0; tm < 2; tm++)
#pragma unroll
            for (int hb = 0; hb < 2; hb++) {
                int rloc = m0w + tm * 16 + lr + hb * 8;
                s_e2[wn][rloc][0] = elp[tm * 2 + hb];
                s_e2[wn][rloc][1] = erp[tm * 2 + hb];
            }
    }

    // ---- h_proj fp16 stores ----
#pragma unroll
    for (int tm = 0; tm < 2; tm++) {
#pragma unroll
        for (int tn = 0; tn < 4; tn++) {
            int row0 = rowBase + m0w + tm * 16 + lr;
            int col = nBase + n0w + tn * 8 + 2 * lc;
            if (row0 < NN)
                g_hproj_h2[(row0 * OUTDIM + col) >> 1] =
                    packh2(acc[tm][tn][0], acc[tm][tn][1]);
            if (row0 + 8 < NN)
                g_hproj_h2[((row0 + 8) * OUTDIM + col) >> 1] =
                    packh2(acc[tm][tn][2], acc[tm][tn][3]);
        }
    }

    __syncthreads();
    if (tid < 128) {
        int gr = rowBase + tid;
        if (gr < NN)
            g_el[gr * NHEAD + blockIdx.y] = s_e2[0][tid][0] + s_e2[1][tid][0];
    } else {
        int t = tid - 128;
        int gr = rowBase + t;
        if (gr < NN)
            g_er[gr * NHEAD + blockIdx.y] = s_e2[0][t][1] + s_e2[1][t][1];
    }
}

// ----------------------------------------------------------------------------
// Kernel 3: attention + residual + GELU + LayerNorm. 128 threads per node.
// (r13 structure: quarter-warp LDG.128 gather, warp-per-head.)
// ----------------------------------------------------------------------------
__global__ __launch_bounds__(128, 12)
void attn_kernel(const int* __restrict__ nidx, const int* __restrict__ nmask,
                 const float* __restrict__ gamma, const float* __restrict__ beta,
                 float* __restrict__ out) {
    const int n = blockIdx.x;
    const int tid = threadIdx.x;
    const int w = tid >> 5;
    const int lane = tid & 31;

    __shared__ float s_ert[NHEAD][MM];          // transposed er
    __shared__ uint2 s_pack[NHEAD][MM];         // {nb, half2(alpha,alpha)}
    __shared__ float s_red[2][NHEAD];

    const int nb = nidx[n * MM + lane];
    const int mk = nmask[n * MM + lane];

    {
        int msrc = 8 * w + lane;
        int nbm = __shfl_sync(0xffffffffu, nb, msrc & 31);
        if (lane < 8) {
            float4 e4 = *reinterpret_cast<const float4*>(&g_er[nbm * NHEAD]);
            s_ert[0][msrc] = e4.x;
            s_ert[1][msrc] = e4.y;
            s_ert[2][msrc] = e4.z;
            s_ert[3][msrc] = e4.w;
        }
    }
    __syncthreads();

    float alpha;
    {
        float e = g_el[n * NHEAD + w] + s_ert[w][lane];
        e = (e >= 0.0f) ? e : 0.2f * e;
        if (mk == 0) e = NEG_INF;
        float mx = e;
#pragma unroll
        for (int off = 16; off > 0; off >>= 1)
            mx = fmaxf(mx, __shfl_xor_sync(0xffffffffu, mx, off));
        float ex = expf(e - mx);
        float sm = ex;
#pragma unroll
        for (int off = 16; off > 0; off >>= 1)
            sm += __shfl_xor_sync(0xffffffffu, sm, off);
        alpha = ex / sm;
    }

    {
        __half2 a2 = __float2half2_rn(alpha);
        s_pack[w][lane] = make_uint2((uint32_t)nb, *reinterpret_cast<uint32_t*>(&a2));
    }
    __syncwarp();

    const int quad = lane >> 3;
    const int sub  = lane & 7;
    const uint4* __restrict__ hp4 = reinterpret_cast<const uint4*>(g_hproj_h2);
    const int rowStride4 = OUTDIM / 8;
    const int coff4 = w * 8 + sub;

    float acc[8];
#pragma unroll
    for (int k = 0; k < 8; k++) acc[k] = 0.0f;

#pragma unroll
    for (int i0 = 0; i0 < 8; i0 += 4) {
        __half2 h0 = __float2half2_rn(0.0f);
        __half2 h1 = h0, h2 = h0, h3 = h0;
#pragma unroll
        for (int i = i0; i < i0 + 4; i++) {
            uint2 p = s_pack[w][4 * i + quad];
            uint4 v = hp4[p.x * rowStride4 + coff4];
            __half2 a2 = *reinterpret_cast<__half2*>(&p.y);
            h0 = __hfma2(a2, *reinterpret_cast<__half2*>(&v.x), h0);
            h1 = __hfma2(a2, *reinterpret_cast<__half2*>(&v.y), h1);
            h2 = __hfma2(a2, *reinterpret_cast<__half2*>(&v.z), h2);
            h3 = __hfma2(a2, *reinterpret_cast<__half2*>(&v.w), h3);
        }
        float2 f0 = __half22float2(h0);
        float2 f1 = __half22float2(h1);
        float2 f2 = __half22float2(h2);
        float2 f3 = __half22float2(h3);
        acc[0] += f0.x; acc[1] += f0.y; acc[2] += f1.x; acc[3] += f1.y;
        acc[4] += f2.x; acc[5] += f2.y; acc[6] += f3.x; acc[7] += f3.y;
    }

#pragma unroll
    for (int k = 0; k < 8; k++) {
        acc[k] += __shfl_xor_sync(0xffffffffu, acc[k], 8);
        acc[k] += __shfl_xor_sync(0xffffffffu, acc[k], 16);
    }

    float ax = acc[2 * quad];
    float ay = acc[2 * quad + 1];
    const int c = w * 64 + sub * 8 + 2 * quad;
    const int coff = w * 32 + sub * 4 + quad;

    uint32_t rv = g_hproj_h2[n * (OUTDIM / 2) + coff];
    float2 res = __half22float2(*reinterpret_cast<__half2*>(&rv));
    float x0 = ax + res.x;
    float x1 = ay + res.y;
    float g0 = 0.5f * x0 * (1.0f + erff(x0 * 0.70710678118654752f));
    float g1 = 0.5f * x1 * (1.0f + erff(x1 * 0.70710678118654752f));

    float s1 = g0 + g1;
    float s2 = g0 * g0 + g1 * g1;
#pragma unroll
    for (int off = 16; off > 0; off >>= 1) {
        s1 += __shfl_xor_sync(0xffffffffu, s1, off);
        s2 += __shfl_xor_sync(0xffffffffu, s2, off);
    }
    if (lane == 0) { s_red[0][w] = s1; s_red[1][w] = s2; }
    __syncthreads();
    float S1 = s_red[0][0] + s_red[0][1] + s_red[0][2] + s_red[0][3];
    float S2 = s_red[1][0] + s_red[1][1] + s_red[1][2] + s_red[1][3];
    float mean = S1 * (1.0f / 256.0f);
    float var = S2 * (1.0f / 256.0f) - mean * mean;
    float inv = rsqrtf(var + LN_EPS);

    float2 gm = *reinterpret_cast<const float2*>(&gamma[c]);
    float2 bt = *reinterpret_cast<const float2*>(&beta[c]);
    float o0 = (g0 - mean) * inv * gm.x + bt.x;
    float o1 = (g1 - mean) * inv * gm.y + bt.y;
    *reinterpret_cast<float2*>(&out[n * OUTDIM + c]) = make_float2(o0, o1);
}

// ----------------------------------------------------------------------------
extern "C" void kernel_launch(void* const* d_in, const int* in_sizes, int n_in,
                              void* d_out, int out_size) {
    const float* h     = (const float*)d_in[0];
    const int*   nidx  = (const int*)  d_in[1];
    const int*   nmask = (const int*)  d_in[2];
    const float* W     = (const float*)d_in[3];
    const float* a_l   = (const float*)d_in[4];
    const float* a_r   = (const float*)d_in[5];
    const float* gamma = (const float*)d_in[6];
    const float* beta  = (const float*)d_in[7];
    float* out = (float*)d_out;

    cudaFuncSetAttribute(gemm_f16_kernel,
                         cudaFuncAttributeMaxDynamicSharedMemorySize, GEMM_SMEM_BYTES);

    dim3 ggrid((NN + 127) / 128, 4);
    gemm_f16_kernel<<<ggrid, 256, GEMM_SMEM_BYTES>>>(h, W, a_l, a_r);
    attn_kernel<<<NN, 128>>>(nidx, nmask, gamma, beta, out);
}

// round 16
// speedup vs baseline: 1.0901x; 1.0901x over previous
#include <cuda_runtime.h>
#include <cuda_fp16.h>
#include <math.h>
#include <stdint.h>

#define NN 20000
#define MM 32
#define INDIM 256
#define OUTDIM 256
#define NHEAD 4
#define HDIM 64
#define LN_EPS 1e-5f
#define NEG_INF -1.0e9f

// scratch buffers (all fp16 pairs packed in uint32)
__device__ uint32_t g_h16[NN * INDIM / 2];        // fp16 copy of input h (~10.2 MB)
__device__ uint32_t g_W16[INDIM * OUTDIM / 2];    // fp16 copy of W (128 KB)
__device__ uint32_t g_hproj_h2[NN * OUTDIM / 2];  // fp16 h_proj (~10.2 MB)
__device__ float    g_el[NN * NHEAD];
__device__ float    g_er[NN * NHEAD];

// ----------------------------------------------------------------------------
// Kernel 0: convert h and W to fp16. Exact-size launch, 2 float4 per thread
// (measured-best shape).
// ----------------------------------------------------------------------------
#define NH4 (NN * INDIM / 4)
#define NW4 (INDIM * OUTDIM / 4)
#define CONV_THREADS ((NH4 + NW4) / 2)

__device__ __forceinline__ uint2 pack2(float4 v) {
    __half2 a = __float22half2_rn(make_float2(v.x, v.y));
    __half2 b = __float22half2_rn(make_float2(v.z, v.w));
    return make_uint2(*reinterpret_cast<uint32_t*>(&a), *reinterpret_cast<uint32_t*>(&b));
}

__global__ __launch_bounds__(256)
void convert_kernel(const float* __restrict__ h, const float* __restrict__ W) {
    int t = blockIdx.x * 256 + threadIdx.x;
    if (t < NH4 / 2) {
        float4 v0 = reinterpret_cast<const float4*>(h)[2 * t];
        float4 v1 = reinterpret_cast<const float4*>(h)[2 * t + 1];
        uint2 p0 = pack2(v0), p1 = pack2(v1);
        *reinterpret_cast<uint4*>(&g_h16[4 * t]) = make_uint4(p0.x, p0.y, p1.x, p1.y);
    } else if (t < CONV_THREADS) {
        int u = t - NH4 / 2;
        float4 v0 = reinterpret_cast<const float4*>(W)[2 * u];
        float4 v1 = reinterpret_cast<const float4*>(W)[2 * u + 1];
        uint2 p0 = pack2(v0), p1 = pack2(v1);
        *reinterpret_cast<uint4*>(&g_W16[4 * u]) = make_uint4(p0.x, p0.y, p1.x, p1.y);
    }
}

// ----------------------------------------------------------------------------
// Common PTX helpers
// ----------------------------------------------------------------------------
__device__ __forceinline__ void cp_async16(uint32_t dst, const void* src, int src_bytes) {
    asm volatile("cp.async.cg.shared.global [%0], [%1], 16, %2;\n"
                 :: "r"(dst), "l"(src), "r"(src_bytes));
}
__device__ __forceinline__ void cp_commit() {
    asm volatile("cp.async.commit_group;\n" ::: "memory");
}
template <int N>
__device__ __forceinline__ void cp_wait() {
    asm volatile("cp.async.wait_group %0;\n" :: "n"(N) : "memory");
}
__device__ __forceinline__ void ldsm_x4(uint32_t& r0, uint32_t& r1, uint32_t& r2,
                                        uint32_t& r3, uint32_t addr) {
    asm volatile("ldmatrix.sync.aligned.m8n8.x4.shared.b16 {%0,%1,%2,%3}, [%4];"
                 : "=r"(r0), "=r"(r1), "=r"(r2), "=r"(r3) : "r"(addr));
}
__device__ __forceinline__ void ldsm_x4_t(uint32_t& r0, uint32_t& r1, uint32_t& r2,
                                          uint32_t& r3, uint32_t addr) {
    asm volatile("ldmatrix.sync.aligned.m8n8.x4.trans.shared.b16 {%0,%1,%2,%3}, [%4];"
                 : "=r"(r0), "=r"(r1), "=r"(r2), "=r"(r3) : "r"(addr));
}
__device__ __forceinline__ void mma_f16(float* d, const uint32_t* a, const uint32_t* b) {
    asm volatile(
        "mma.sync.aligned.m16n8k16.row.col.f32.f16.f16.f32 "
        "{%0,%1,%2,%3}, {%4,%5,%6,%7}, {%8,%9}, {%0,%1,%2,%3};"
        : "+f"(d[0]), "+f"(d[1]), "+f"(d[2]), "+f"(d[3])
        : "r"(a[0]), "r"(a[1]), "r"(a[2]), "r"(a[3]), "r"(b[0]), "r"(b[1]));
}

// ----------------------------------------------------------------------------
// Kernel 1: h_proj = h @ W, fp16 mma.sync m16n8k16, 4-stage cp.async, ldmatrix.
// Block tile 128x64, BK=32, 256 threads (8 warps: 4M x 2N), warp tile 32x32.
// Epilogue computes el/er for head blockIdx.y.
// ----------------------------------------------------------------------------
#define BKG 32
#define A_ST 40
#define B_ST 72
#define A_HALFS (128 * A_ST)
#define B_HALFS (BKG * B_ST)
#define STAGE_BYTES ((A_HALFS + B_HALFS) * 2)
#define NSTG 4
#define GEMM_SMEM_BYTES (NSTG * STAGE_BYTES)

__global__ __launch_bounds__(256, 3)
void gemm_f16_kernel(const float* __restrict__ a_l, const float* __restrict__ a_r) {
    extern __shared__ uint8_t dynsm[];
    const uint32_t smem_base = (uint32_t)__cvta_generic_to_shared(dynsm);
    __shared__ float s_e2[2][128][2];   // [wn][row][el/er]

    const int tid = threadIdx.x;
    const int lane = tid & 31;
    const int w = tid >> 5;
    const int wm = w & 3;
    const int wn = w >> 2;
    const int m0w = wm * 32;
    const int n0w = wn * 32;

    const int rowBase = blockIdx.x * 128;
    const int nBase = blockIdx.y * 64;

    const int a_row0 = tid >> 2;
    const int a_ch   = (tid & 3) * 8;
    const int b_row  = tid >> 3;
    const int b_ch   = (tid & 7) * 8;

    auto issue_copies = [&](int stage, int kt) {
        uint32_t aB = smem_base + stage * STAGE_BYTES;
        uint32_t bB = aB + A_HALFS * 2;
#pragma unroll
        for (int q = 0; q < 2; q++) {
            int r = a_row0 + 64 * q;
            int gr = rowBase + r;
            int sz = (gr < NN) ? 16 : 0;
            cp_async16(aB + (r * A_ST + a_ch) * 2,
                       &g_h16[(gr * INDIM + kt + a_ch) >> 1], sz);
        }
        cp_async16(bB + (b_row * B_ST + b_ch) * 2,
                   &g_W16[((kt + b_row) * OUTDIM + nBase + b_ch) >> 1], 16);
    };

    float acc[2][4][4];
#pragma unroll
    for (int i = 0; i < 2; i++)
#pragma unroll
        for (int j = 0; j < 4; j++)
#pragma unroll
            for (int k = 0; k < 4; k++) acc[i][j][k] = 0.0f;

    const int r8 = lane & 7;
    const int quad = lane >> 3;
    const int qRow = (quad & 1) << 3;
    const int qCol = (quad >> 1) << 3;

    issue_copies(0, 0);  cp_commit();
    issue_copies(1, BKG); cp_commit();
    issue_copies(2, 2 * BKG); cp_commit();

    const int NITER = INDIM / BKG;
    for (int it = 0; it < NITER; it++) {
        cp_wait<2>();
        __syncthreads();
        const uint32_t sA = smem_base + (it & (NSTG - 1)) * STAGE_BYTES;
        const uint32_t sB = sA + A_HALFS * 2;

#pragma unroll
        for (int g = 0; g < 2; g++) {
            const int k0 = g * 16;
            uint32_t a[2][4];
#pragma unroll
            for (int tm = 0; tm < 2; tm++) {
                uint32_t addr = sA + ((m0w + tm * 16 + qRow + r8) * A_ST + k0 + qCol) * 2;
                ldsm_x4(a[tm][0], a[tm][1], a[tm][2], a[tm][3], addr);
            }
            uint32_t b[2][4];
#pragma unroll
            for (int t2 = 0; t2 < 2; t2++) {
                uint32_t addr = sB + ((k0 + qRow + r8) * B_ST + n0w + t2 * 16 + qCol) * 2;
                ldsm_x4_t(b[t2][0], b[t2][1], b[t2][2], b[t2][3], addr);
            }
#pragma unroll
            for (int tm = 0; tm < 2; tm++)
#pragma unroll
                for (int tn = 0; tn < 4; tn++) {
                    uint32_t bb[2] = { b[tn >> 1][2 * (tn & 1)], b[tn >> 1][2 * (tn & 1) + 1] };
                    mma_f16(acc[tm][tn], a[tm], bb);
                }
        }

        if (it + 3 < NITER)
            issue_copies((it + 3) & (NSTG - 1), (it + 3) * BKG);
        cp_commit();
    }

    const int lr = lane >> 2;
    const int lc = lane & 3;

    // ---- el/er partials for head blockIdx.y ----
    float alv[8], arv[8];
#pragma unroll
    for (int tn = 0; tn < 4; tn++)
#pragma unroll
        for (int kk = 0; kk < 2; kk++) {
            int c = nBase + n0w + tn * 8 + 2 * lc + kk;
            alv[tn * 2 + kk] = a_l[c];
            arv[tn * 2 + kk] = a_r[c];
        }
    float elp[4] = {0.f, 0.f, 0.f, 0.f};
    float erp[4] = {0.f, 0.f, 0.f, 0.f};
#pragma unroll
    for (int tm = 0; tm < 2; tm++)
#pragma unroll
        for (int tn = 0; tn < 4; tn++)
#pragma unroll
            for (int k = 0; k < 4; k++) {
                int ridx = tm * 2 + (k >> 1);
                float av = alv[tn * 2 + (k & 1)];
                float rv = arv[tn * 2 + (k & 1)];
                elp[ridx] = fmaf(acc[tm][tn][k], av, elp[ridx]);
                erp[ridx] = fmaf(acc[tm][tn][k], rv, erp[ridx]);
            }
#pragma unroll
    for (int off = 1; off <= 2; off <<= 1)
#pragma unroll
        for (int i = 0; i < 4; i++) {
            elp[i] += __shfl_xor_sync(0xffffffffu, elp[i], off);
            erp[i] += __shfl_xor_sync(0xffffffffu, erp[i], off);
        }
    if (lc == 0) {
#pragma unroll
        for (int tm = 0; tm < 2; tm++)
#pragma unroll
            for (int hb = 0; hb < 2; hb++) {
                int rloc = m0w + tm * 16 + lr + hb * 8;
                s_e2[wn][rloc][0] = elp[tm * 2 + hb];
                s_e2[wn][rloc][1] = erp[tm * 2 + hb];
            }
    }

    // ---- h_proj fp16 stores ----
#pragma unroll
    for (int tm = 0; tm < 2; tm++) {
#pragma unroll
        for (int tn = 0; tn < 4; tn++) {
            int row0 = rowBase + m0w + tm * 16 + lr;
            int col = nBase + n0w + tn * 8 + 2 * lc;
            if (row0 < NN) {
                __half2 v = __float22half2_rn(make_float2(acc[tm][tn][0], acc[tm][tn][1]));
                g_hproj_h2[(row0 * OUTDIM + col) >> 1] = *reinterpret_cast<uint32_t*>(&v);
            }
            if (row0 + 8 < NN) {
                __half2 v = __float22half2_rn(make_float2(acc[tm][tn][2], acc[tm][tn][3]));
                g_hproj_h2[((row0 + 8) * OUTDIM + col) >> 1] = *reinterpret_cast<uint32_t*>(&v);
            }
        }
    }

    __syncthreads();
    if (tid < 128) {
        int gr = rowBase + tid;
        if (gr < NN)
            g_el[gr * NHEAD + blockIdx.y] = s_e2[0][tid][0] + s_e2[1][tid][0];
    } else {
        int t = tid - 128;
        int gr = rowBase + t;
        if (gr < NN)
            g_er[gr * NHEAD + blockIdx.y] = s_e2[0][t][1] + s_e2[1][t][1];
    }
}

// ----------------------------------------------------------------------------
// Kernel 3: attention + residual + GELU + LayerNorm. 128 threads per node.
// Warp w owns head w end-to-end. Quarter-warp LDG.128 gather; s_pack stores
// the PRE-SCALED row offset (nb * 32 uint4 units) so the per-load index is a
// single IADD (removes the per-load IMAD chain from the hot loop).
// ----------------------------------------------------------------------------
__global__ __launch_bounds__(128, 12)
void attn_kernel(const int* __restrict__ nidx, const int* __restrict__ nmask,
                 const float* __restrict__ gamma, const float* __restrict__ beta,
                 float* __restrict__ out) {
    const int n = blockIdx.x;
    const int tid = threadIdx.x;
    const int w = tid >> 5;
    const int lane = tid & 31;

    __shared__ float s_ert[NHEAD][MM];          // transposed er
    __shared__ uint2 s_pack[NHEAD][MM];         // {nb*32, half2(alpha,alpha)}
    __shared__ float s_red[2][NHEAD];

    const int nb = nidx[n * MM + lane];
    const int mk = nmask[n * MM + lane];

    {
        int msrc = 8 * w + lane;
        int nbm = __shfl_sync(0xffffffffu, nb, msrc & 31);
        if (lane < 8) {
            float4 e4 = *reinterpret_cast<const float4*>(&g_er[nbm * NHEAD]);
            s_ert[0][msrc] = e4.x;
            s_ert[1][msrc] = e4.y;
            s_ert[2][msrc] = e4.z;
            s_ert[3][msrc] = e4.w;
        }
    }
    __syncthreads();

    float alpha;
    {
        float e = g_el[n * NHEAD + w] + s_ert[w][lane];
        e = (e >= 0.0f) ? e : 0.2f * e;
        if (mk == 0) e = NEG_INF;
        float mx = e;
#pragma unroll
        for (int off = 16; off > 0; off >>= 1)
            mx = fmaxf(mx, __shfl_xor_sync(0xffffffffu, mx, off));
        float ex = expf(e - mx);
        float sm = ex;
#pragma unroll
        for (int off = 16; off > 0; off >>= 1)
            sm += __shfl_xor_sync(0xffffffffu, sm, off);
        alpha = ex / sm;
    }

    {
        __half2 a2 = __float2half2_rn(alpha);
        // pre-scaled row offset in uint4 units (row stride = OUTDIM/8 = 32)
        s_pack[w][lane] = make_uint2((uint32_t)nb * (OUTDIM / 8),
                                     *reinterpret_cast<uint32_t*>(&a2));
    }
    __syncwarp();

    const int quad = lane >> 3;
    const int sub  = lane & 7;
    const uint4* __restrict__ hp4 = reinterpret_cast<const uint4*>(g_hproj_h2);
    const int coff4 = w * 8 + sub;

    float acc[8];
#pragma unroll
    for (int k = 0; k < 8; k++) acc[k] = 0.0f;

#pragma unroll
    for (int i0 = 0; i0 < 8; i0 += 4) {
        __half2 h0 = __float2half2_rn(0.0f);
        __half2 h1 = h0, h2 = h0, h3 = h0;
#pragma unroll
        for (int i = i0; i < i0 + 4; i++) {
            uint2 p = s_pack[w][4 * i + quad];
            uint4 v = hp4[p.x + coff4];          // single IADD index
            __half2 a2 = *reinterpret_cast<__half2*>(&p.y);
            h0 = __hfma2(a2, *reinterpret_cast<__half2*>(&v.x), h0);
            h1 = __hfma2(a2, *reinterpret_cast<__half2*>(&v.y), h1);
            h2 = __hfma2(a2, *reinterpret_cast<__half2*>(&v.z), h2);
            h3 = __hfma2(a2, *reinterpret_cast<__half2*>(&v.w), h3);
        }
        float2 f0 = __half22float2(h0);
        float2 f1 = __half22float2(h1);
        float2 f2 = __half22float2(h2);
        float2 f3 = __half22float2(h3);
        acc[0] += f0.x; acc[1] += f0.y; acc[2] += f1.x; acc[3] += f1.y;
        acc[4] += f2.x; acc[5] += f2.y; acc[6] += f3.x; acc[7] += f3.y;
    }

#pragma unroll
    for (int k = 0; k < 8; k++) {
        acc[k] += __shfl_xor_sync(0xffffffffu, acc[k], 8);
        acc[k] += __shfl_xor_sync(0xffffffffu, acc[k], 16);
    }

    float ax = acc[2 * quad];
    float ay = acc[2 * quad + 1];
    const int c = w * 64 + sub * 8 + 2 * quad;
    const int coff = w * 32 + sub * 4 + quad;

    uint32_t rv = g_hproj_h2[n * (OUTDIM / 2) + coff];
    float2 res = __half22float2(*reinterpret_cast<__half2*>(&rv));
    float x0 = ax + res.x;
    float x1 = ay + res.y;
    float g0 = 0.5f * x0 * (1.0f + erff(x0 * 0.70710678118654752f));
    float g1 = 0.5f * x1 * (1.0f + erff(x1 * 0.70710678118654752f));

    float s1 = g0 + g1;
    float s2 = g0 * g0 + g1 * g1;
#pragma unroll
    for (int off = 16; off > 0; off >>= 1) {
        s1 += __shfl_xor_sync(0xffffffffu, s1, off);
        s2 += __shfl_xor_sync(0xffffffffu, s2, off);
    }
    if (lane == 0) { s_red[0][w] = s1; s_red[1][w] = s2; }
    __syncthreads();
    float S1 = s_red[0][0] + s_red[0][1] + s_red[0][2] + s_red[0][3];
    float S2 = s_red[1][0] + s_red[1][1] + s_red[1][2] + s_red[1][3];
    float mean = S1 * (1.0f / 256.0f);
    float var = S2 * (1.0f / 256.0f) - mean * mean;
    float inv = rsqrtf(var + LN_EPS);

    float2 gm = *reinterpret_cast<const float2*>(&gamma[c]);
    float2 bt = *reinterpret_cast<const float2*>(&beta[c]);
    float o0 = (g0 - mean) * inv * gm.x + bt.x;
    float o1 = (g1 - mean) * inv * gm.y + bt.y;
    *reinterpret_cast<float2*>(&out[n * OUTDIM + c]) = make_float2(o0, o1);
}

// ----------------------------------------------------------------------------
extern "C" void kernel_launch(void* const* d_in, const int* in_sizes, int n_in,
                              void* d_out, int out_size) {
    const float* h     = (const float*)d_in[0];
    const int*   nidx  = (const int*)  d_in[1];
    const int*   nmask = (const int*)  d_in[2];
    const float* W     = (const float*)d_in[3];
    const float* a_l   = (const float*)d_in[4];
    const float* a_r   = (const float*)d_in[5];
    const float* gamma = (const float*)d_in[6];
    const float* beta  = (const float*)d_in[7];
    float* out = (float*)d_out;

    cudaFuncSetAttribute(gemm_f16_kernel,
                         cudaFuncAttributeMaxDynamicSharedMemorySize, GEMM_SMEM_BYTES);

    convert_kernel<<<(CONV_THREADS + 255) / 256, 256>>>(h, W);
    dim3 ggrid((NN + 127) / 128, 4);
    gemm_f16_kernel<<<ggrid, 256, GEMM_SMEM_BYTES>>>(a_l, a_r);
    attn_kernel<<<NN, 128>>>(nidx, nmask, gamma, beta, out);
}